// round 6
// baseline (speedup 1.0000x reference)
#include <cuda_runtime.h>
#include <cuda_bf16.h>
#include <math.h>

// ---------------------------------------------------------------------------
// TransformerEncoderBlock: B=4, S=2048, D=1024, H=16, Dk=64, Dff=4096, fp32.
// Round 6: mma.sync GEMM with 128x256 CTA tiles, 64x64 warp tiles, ldmatrix
// fragment loads (tensor-issue bound). tcgen05 unavailable (harness builds
// PTX at compute_103 without 'a' features). Attention: R4 mma flash kernel.
// ---------------------------------------------------------------------------

#define BATCH   4
#define SEQ     2048
#define DMODEL  1024
#define NHEADS  16
#define DK      64
#define DFF     4096
#define MROWS   (BATCH * SEQ)   // 8192

// ---------------- scratch (__device__ globals; no allocs allowed) ----------
__device__ float g_x1[MROWS * DMODEL];

__device__ __align__(16) __nv_bfloat16 g_hh  [MROWS * DMODEL];
__device__ __align__(16) __nv_bfloat16 g_hl  [MROWS * DMODEL];
__device__ __align__(16) __nv_bfloat16 g_qh  [MROWS * DMODEL];
__device__ __align__(16) __nv_bfloat16 g_ql  [MROWS * DMODEL];
__device__ __align__(16) __nv_bfloat16 g_kh  [MROWS * DMODEL];
__device__ __align__(16) __nv_bfloat16 g_kl  [MROWS * DMODEL];
__device__ __align__(16) __nv_bfloat16 g_vh  [MROWS * DMODEL];
__device__ __align__(16) __nv_bfloat16 g_vl  [MROWS * DMODEL];
__device__ __align__(16) __nv_bfloat16 g_ctxh[MROWS * DMODEL];
__device__ __align__(16) __nv_bfloat16 g_ctxl[MROWS * DMODEL];
__device__ __align__(16) __nv_bfloat16 g_h2h [MROWS * DMODEL];
__device__ __align__(16) __nv_bfloat16 g_h2l [MROWS * DMODEL];
__device__ __align__(16) __nv_bfloat16 g_ffnh[MROWS * DFF];
__device__ __align__(16) __nv_bfloat16 g_ffnl[MROWS * DFF];

__device__ __align__(16) __nv_bfloat16 g_wqh[DMODEL*DMODEL], g_wql[DMODEL*DMODEL];
__device__ __align__(16) __nv_bfloat16 g_wkh[DMODEL*DMODEL], g_wkl[DMODEL*DMODEL];
__device__ __align__(16) __nv_bfloat16 g_wvh[DMODEL*DMODEL], g_wvl[DMODEL*DMODEL];
__device__ __align__(16) __nv_bfloat16 g_woh[DMODEL*DMODEL], g_wol[DMODEL*DMODEL];
__device__ __align__(16) __nv_bfloat16 g_w1h[DFF*DMODEL],    g_w1l[DFF*DMODEL];
__device__ __align__(16) __nv_bfloat16 g_w2h[DMODEL*DFF],    g_w2l[DMODEL*DFF];

// ---------------------------------------------------------------------------
__device__ __forceinline__ void split_bf16(float v, __nv_bfloat16& hi, __nv_bfloat16& lo) {
    hi = __float2bfloat16(v);
    lo = __float2bfloat16(v - __bfloat162float(hi));
}
__device__ __forceinline__ float gelu_exact(float x) {
    return 0.5f * x * (1.0f + erff(x * 0.70710678118654752f));
}
__device__ __forceinline__ void cp16(const void* dst_smem, const void* src) {
    unsigned s = (unsigned)__cvta_generic_to_shared(dst_smem);
    asm volatile("cp.async.cg.shared.global [%0], [%1], 16;\n" :: "r"(s), "l"(src));
}
__device__ __forceinline__ void cp16u(unsigned dst_smem, const void* src) {
    asm volatile("cp.async.cg.shared.global [%0], [%1], 16;\n" :: "r"(dst_smem), "l"(src));
}
__device__ __forceinline__ void mma_bf16(float* c, const unsigned* a, const unsigned* b) {
    asm volatile(
        "mma.sync.aligned.m16n8k16.row.col.f32.bf16.bf16.f32 "
        "{%0,%1,%2,%3}, {%4,%5,%6,%7}, {%8,%9}, {%0,%1,%2,%3};\n"
        : "+f"(c[0]), "+f"(c[1]), "+f"(c[2]), "+f"(c[3])
        : "r"(a[0]), "r"(a[1]), "r"(a[2]), "r"(a[3]), "r"(b[0]), "r"(b[1]));
}
__device__ __forceinline__ void ldsm4(unsigned& r0, unsigned& r1, unsigned& r2, unsigned& r3, unsigned addr) {
    asm volatile("ldmatrix.sync.aligned.m8n8.x4.shared.b16 {%0,%1,%2,%3}, [%4];"
                 : "=r"(r0), "=r"(r1), "=r"(r2), "=r"(r3) : "r"(addr));
}
__device__ __forceinline__ void ldsm4t(unsigned& r0, unsigned& r1, unsigned& r2, unsigned& r3, unsigned addr) {
    asm volatile("ldmatrix.sync.aligned.m8n8.x4.trans.shared.b16 {%0,%1,%2,%3}, [%4];"
                 : "=r"(r0), "=r"(r1), "=r"(r2), "=r"(r3) : "r"(addr));
}
// FFMA-only e^x for x <= 0 (clamped). rel err ~4e-5.
__device__ __forceinline__ float fexp(float x) {
    x = fmaxf(x, -60.0f);
    float t = x * 1.4426950408889634f;
    float z = t + 12582912.0f;
    int   e = __float_as_int(z) - 0x4B400000;
    float f = t - (z - 12582912.0f);
    float p = 0.0096181291f;
    p = fmaf(p, f, 0.0555041087f);
    p = fmaf(p, f, 0.2402265070f);
    p = fmaf(p, f, 0.6931471806f);
    p = fmaf(p, f, 1.0f);
    return __int_as_float(__float_as_int(p) + (e << 23));
}
__device__ __forceinline__ void pack_hilo(float a, float b, unsigned& hi, unsigned& lo) {
    __nv_bfloat162 h2 = __float22bfloat162_rn(make_float2(a, b));
    float2 hf = __bfloat1622float2(h2);
    __nv_bfloat162 l2 = __float22bfloat162_rn(make_float2(a - hf.x, b - hf.y));
    hi = *(unsigned*)&h2;
    lo = *(unsigned*)&l2;
}

// ---------------------------------------------------------------------------
// Weight split + transpose:  W[K][N] fp32  ->  Th/Tl[N][K] bf16
// ---------------------------------------------------------------------------
__global__ __launch_bounds__(256) void wsplit_kernel(
    const float* __restrict__ W, __nv_bfloat16* __restrict__ Th,
    __nv_bfloat16* __restrict__ Tl, int K, int N)
{
    __shared__ float tile[32][33];
    int n0 = blockIdx.x * 32, k0 = blockIdx.y * 32;
    int tx = threadIdx.x & 31;
    int ty = threadIdx.x >> 5;
    #pragma unroll
    for (int i = 0; i < 32; i += 8)
        tile[ty + i][tx] = W[(size_t)(k0 + ty + i) * N + n0 + tx];
    __syncthreads();
    #pragma unroll
    for (int i = 0; i < 32; i += 8) {
        float v = tile[tx][ty + i];
        __nv_bfloat16 hi, lo; split_bf16(v, hi, lo);
        size_t o = (size_t)(n0 + ty + i) * K + k0 + tx;
        Th[o] = hi; Tl[o] = lo;
    }
}

// ---------------------------------------------------------------------------
// LayerNorm -> bf16 hi/lo outputs.
// ---------------------------------------------------------------------------
__global__ __launch_bounds__(256) void ln_kernel(
    const float* __restrict__ x, const float* __restrict__ gamma,
    const float* __restrict__ beta,
    __nv_bfloat16* __restrict__ out_hi, __nv_bfloat16* __restrict__ out_lo)
{
    int row = blockIdx.x;
    int tid = threadIdx.x;
    const float4* xr = (const float4*)(x + (size_t)row * DMODEL);
    float4 v = xr[tid];

    __shared__ float red[256];
    red[tid] = v.x + v.y + v.z + v.w; __syncthreads();
    #pragma unroll
    for (int off = 128; off > 0; off >>= 1) {
        if (tid < off) red[tid] += red[tid + off];
        __syncthreads();
    }
    float mu = red[0] * (1.0f / DMODEL);
    __syncthreads();

    float dx0 = v.x - mu, dx1 = v.y - mu, dx2 = v.z - mu, dx3 = v.w - mu;
    red[tid] = dx0*dx0 + dx1*dx1 + dx2*dx2 + dx3*dx3; __syncthreads();
    #pragma unroll
    for (int off = 128; off > 0; off >>= 1) {
        if (tid < off) red[tid] += red[tid + off];
        __syncthreads();
    }
    float rs = rsqrtf(red[0] * (1.0f / DMODEL) + 1e-5f);

    float4 g4 = ((const float4*)gamma)[tid];
    float4 b4 = ((const float4*)beta)[tid];
    float o0 = dx0 * rs * g4.x + b4.x;
    float o1 = dx1 * rs * g4.y + b4.y;
    float o2 = dx2 * rs * g4.z + b4.z;
    float o3 = dx3 * rs * g4.w + b4.w;

    unsigned h01, l01, h23, l23;
    pack_hilo(o0, o1, h01, l01);
    pack_hilo(o2, o3, h23, l23);
    size_t o = (size_t)row * DMODEL + tid * 4;
    *(unsigned*)&out_hi[o]   = h01; *(unsigned*)&out_hi[o+2] = h23;
    *(unsigned*)&out_lo[o]   = l01; *(unsigned*)&out_lo[o+2] = l23;
}

// ---------------------------------------------------------------------------
// bf16x3 MMA GEMM v2: C[M,N] = (Ah+Al)[M,K] @ (Bh+Bl)^T[N,K] + bias (+R|gelu)
// CTA tile 128x256, 256 threads (8 warps, 2x4), warp tile 64x64.
// k-tile 16; rows padded to 24 bf16 (48B) -> conflict-free ldmatrix.
// EPI: 1 bias+R->f32 | 2 bias+gelu->bf16 hi/lo | 3 bias->bf16 hi/lo
// ---------------------------------------------------------------------------
#define G2_AS_H  0
#define G2_AS_L  6144
#define G2_BS_H  12288
#define G2_BS_L  24576
#define G2_STAGE 36864
#define G2_SMEM  (2 * G2_STAGE)     // 73728 bytes

template<int EPI>
__global__ __launch_bounds__(256) void mma_gemm2(
    const __nv_bfloat16* __restrict__ Ah, const __nv_bfloat16* __restrict__ Al,
    const __nv_bfloat16* __restrict__ Bh, const __nv_bfloat16* __restrict__ Bl,
    const float* __restrict__ bias, const float* __restrict__ R,
    float* __restrict__ C, __nv_bfloat16* __restrict__ Chi,
    __nv_bfloat16* __restrict__ Clo, int M, int N, int K)
{
    extern __shared__ __align__(16) char sm2[];
    const unsigned smb = (unsigned)__cvta_generic_to_shared(sm2);

    const int tid  = threadIdx.x;
    const int warp = tid >> 5;
    const int lane = tid & 31;
    const int warpm = warp >> 2;       // 0..1
    const int warpn = warp & 3;        // 0..3
    const int g = lane >> 2;
    const int c = lane & 3;
    const int bm = blockIdx.y * 128;
    const int bn = blockIdx.x * 256;

    float acc[4][8][4];
    #pragma unroll
    for (int i = 0; i < 4; i++)
        #pragma unroll
        for (int j = 0; j < 8; j++)
            #pragma unroll
            for (int r = 0; r < 4; r++) acc[i][j][r] = 0.0f;

    // stage loader: Ah/Al 128 rows x 2 16B-halves, Bh/Bl 256 rows x 2 halves
    auto load_stage = [&](int s, int kt) {
        const unsigned sb = smb + s * G2_STAGE;
        const int k0 = kt * 16;
        {
            int r = tid >> 1, hf = tid & 1;
            size_t ga = (size_t)(bm + r) * K + k0 + hf * 8;
            unsigned d = (unsigned)(r * 48 + hf * 16);
            cp16u(sb + G2_AS_H + d, Ah + ga);
            cp16u(sb + G2_AS_L + d, Al + ga);
        }
        #pragma unroll
        for (int j = 0; j < 2; j++) {
            int idx = tid + j * 256;
            int r = idx >> 1, hf = idx & 1;
            size_t gb = (size_t)(bn + r) * K + k0 + hf * 8;
            unsigned d = (unsigned)(r * 48 + hf * 16);
            cp16u(sb + G2_BS_H + d, Bh + gb);
            cp16u(sb + G2_BS_L + d, Bl + gb);
        }
        asm volatile("cp.async.commit_group;\n" ::);
    };

    const int nk = K >> 4;
    load_stage(0, 0);

    // ldmatrix lane addressing: rows = (lane&15), k-half = lane>>4
    const unsigned afrag = (unsigned)((warpm * 64 + (lane & 15)) * 48 + (lane >> 4) * 16);
    const unsigned bfrag = (unsigned)((warpn * 64 + (lane & 15)) * 48 + (lane >> 4) * 16);

    for (int t = 0; t < nk; t++) {
        asm volatile("cp.async.wait_group 0;\n" ::);
        __syncthreads();
        if (t + 1 < nk) load_stage((t + 1) & 1, t + 1);

        const unsigned sb = smb + (t & 1) * G2_STAGE;

        unsigned ah[4][4], al[4][4], bh[8][2], bl[8][2];
        #pragma unroll
        for (int mi = 0; mi < 4; mi++)
            ldsm4(ah[mi][0], ah[mi][1], ah[mi][2], ah[mi][3],
                  sb + G2_AS_H + afrag + mi * 768);
        #pragma unroll
        for (int nb = 0; nb < 4; nb++) {
            unsigned r0, r1, r2, r3;
            ldsm4(r0, r1, r2, r3, sb + G2_BS_H + bfrag + nb * 768);
            bh[2*nb][0] = r0; bh[2*nb][1] = r2;
            bh[2*nb+1][0] = r1; bh[2*nb+1][1] = r3;
        }
        #pragma unroll
        for (int mi = 0; mi < 4; mi++)
            #pragma unroll
            for (int ni = 0; ni < 8; ni++)
                mma_bf16(acc[mi][ni], ah[mi], bh[ni]);

        #pragma unroll
        for (int mi = 0; mi < 4; mi++)
            ldsm4(al[mi][0], al[mi][1], al[mi][2], al[mi][3],
                  sb + G2_AS_L + afrag + mi * 768);
        #pragma unroll
        for (int mi = 0; mi < 4; mi++)
            #pragma unroll
            for (int ni = 0; ni < 8; ni++)
                mma_bf16(acc[mi][ni], al[mi], bh[ni]);

        #pragma unroll
        for (int nb = 0; nb < 4; nb++) {
            unsigned r0, r1, r2, r3;
            ldsm4(r0, r1, r2, r3, sb + G2_BS_L + bfrag + nb * 768);
            bl[2*nb][0] = r0; bl[2*nb][1] = r2;
            bl[2*nb+1][0] = r1; bl[2*nb+1][1] = r3;
        }
        #pragma unroll
        for (int mi = 0; mi < 4; mi++)
            #pragma unroll
            for (int ni = 0; ni < 8; ni++)
                mma_bf16(acc[mi][ni], ah[mi], bl[ni]);
    }

    // epilogue
    #pragma unroll
    for (int mi = 0; mi < 4; mi++) {
        int r0 = bm + warpm * 64 + mi * 16 + g;
        #pragma unroll
        for (int ni = 0; ni < 8; ni++) {
            int col = bn + warpn * 64 + ni * 8 + c * 2;
            float2 bia = *(const float2*)&bias[col];
            float v0 = acc[mi][ni][0] + bia.x;
            float v1 = acc[mi][ni][1] + bia.y;
            float v2 = acc[mi][ni][2] + bia.x;
            float v3 = acc[mi][ni][3] + bia.y;
            size_t o0 = (size_t)r0 * N + col;
            size_t o1 = (size_t)(r0 + 8) * N + col;
            if (EPI == 1) {
                float2 ra = *(const float2*)&R[o0];
                float2 rb = *(const float2*)&R[o1];
                v0 += ra.x; v1 += ra.y; v2 += rb.x; v3 += rb.y;
                *(float2*)&C[o0] = make_float2(v0, v1);
                *(float2*)&C[o1] = make_float2(v2, v3);
            } else {
                if (EPI == 2) {
                    v0 = gelu_exact(v0); v1 = gelu_exact(v1);
                    v2 = gelu_exact(v2); v3 = gelu_exact(v3);
                }
                unsigned h01, l01, h23, l23;
                pack_hilo(v0, v1, h01, l01);
                pack_hilo(v2, v3, h23, l23);
                *(unsigned*)&Chi[o0] = h01; *(unsigned*)&Chi[o1] = h23;
                *(unsigned*)&Clo[o0] = l01; *(unsigned*)&Clo[o1] = l23;
            }
        }
    }
}

// ---------------------------------------------------------------------------
// Tensor-core flash attention (R4, unchanged).
// ---------------------------------------------------------------------------
#define ATT_QH   0
#define ATT_QL   8192
#define ATT_KH   16384
#define ATT_TILE 8192
#define ATT_FM   (16384 + 2*32768)
#define ATT_SMEM (ATT_FM + 2*64*4)

__device__ __forceinline__ unsigned swz(unsigned base, int row, int cc) {
    return base + (unsigned)((row << 7) + (((cc ^ row) & 7) << 4));
}

__global__ __launch_bounds__(128) void attn_mma(
    const __nv_bfloat16* __restrict__ Qh, const __nv_bfloat16* __restrict__ Ql,
    const __nv_bfloat16* __restrict__ Kh, const __nv_bfloat16* __restrict__ Kl,
    const __nv_bfloat16* __restrict__ Vh, const __nv_bfloat16* __restrict__ Vl,
    const int* __restrict__ mask,
    __nv_bfloat16* __restrict__ Ohi, __nv_bfloat16* __restrict__ Olo)
{
    extern __shared__ __align__(16) char sm[];
    const unsigned smb = (unsigned)__cvta_generic_to_shared(sm);
    float* fmask = (float*)(sm + ATT_FM);

    const int b  = blockIdx.z;
    const int h  = blockIdx.y;
    const int qt = blockIdx.x;
    const int tid  = threadIdx.x;
    const int warp = tid >> 5;
    const int lane = tid & 31;
    const int li  = lane & 7;
    const int grp = lane >> 3;
    const int g = lane >> 2;
    const int c = lane & 3;

    const int qrow0 = qt * 64;
    const size_t rowQ = (size_t)(b * SEQ + qrow0);

    {
        #pragma unroll
        for (int i = 0; i < 4; i++) {
            int idx = tid + i * 128;
            int row = idx >> 3, cc = idx & 7;
            const __nv_bfloat16* sq = Qh + (rowQ + row) * DMODEL + h * DK + cc * 8;
            const __nv_bfloat16* sq2 = Ql + (rowQ + row) * DMODEL + h * DK + cc * 8;
            cp16(sm + swz(ATT_QH, row, cc), sq);
            cp16(sm + swz(ATT_QL, row, cc), sq2);
        }
        #pragma unroll
        for (int i = 0; i < 4; i++) {
            int idx = tid + i * 128;
            int row = idx >> 3, cc = idx & 7;
            size_t gr = (size_t)(b * SEQ + row) * DMODEL + h * DK + cc * 8;
            cp16(sm + swz(ATT_KH, row, cc), Kh + gr);
            cp16(sm + swz(ATT_KH + ATT_TILE, row, cc), Kl + gr);
            cp16(sm + swz(ATT_KH + 2*ATT_TILE, row, cc), Vh + gr);
            cp16(sm + swz(ATT_KH + 3*ATT_TILE, row, cc), Vl + gr);
        }
        if (tid < 64) fmask[tid] = (mask[b * SEQ + tid] != 0) ? 0.0f : -1e30f;
        asm volatile("cp.async.commit_group;\n" ::);
    }

    float oacc[8][4];
    #pragma unroll
    for (int nt = 0; nt < 8; nt++)
        #pragma unroll
        for (int r = 0; r < 4; r++) oacc[nt][r] = 0.0f;
    float m0 = -1e30f, m1 = -1e30f, l0 = 0.0f, l1 = 0.0f;
    unsigned qfh[4][4], qfl[4][4];

    const int NT = SEQ / 64;
    for (int kt = 0; kt < NT; kt++) {
        asm volatile("cp.async.wait_group 0;\n" ::);
        __syncthreads();

        if (kt == 0) {
            int qrow = warp * 16 + ((grp & 1) << 3) + li;
            #pragma unroll
            for (int q = 0; q < 4; q++) {
                int cc = 2 * q + (grp >> 1);
                ldsm4(qfh[q][0], qfh[q][1], qfh[q][2], qfh[q][3], smb + swz(ATT_QH, qrow, cc));
                ldsm4(qfl[q][0], qfl[q][1], qfl[q][2], qfl[q][3], smb + swz(ATT_QL, qrow, cc));
            }
        }

        if (kt + 1 < NT) {
            int s = (kt + 1) & 1;
            int kb = (kt + 1) * 64;
            #pragma unroll
            for (int i = 0; i < 4; i++) {
                int idx = tid + i * 128;
                int row = idx >> 3, cc = idx & 7;
                size_t gr = (size_t)(b * SEQ + kb + row) * DMODEL + h * DK + cc * 8;
                cp16(sm + swz(ATT_KH + s*32768, row, cc), Kh + gr);
                cp16(sm + swz(ATT_KH + s*32768 + ATT_TILE, row, cc), Kl + gr);
                cp16(sm + swz(ATT_KH + s*32768 + 2*ATT_TILE, row, cc), Vh + gr);
                cp16(sm + swz(ATT_KH + s*32768 + 3*ATT_TILE, row, cc), Vl + gr);
            }
            if (tid < 64) fmask[s * 64 + tid] = (mask[b * SEQ + kb + tid] != 0) ? 0.0f : -1e30f;
            asm volatile("cp.async.commit_group;\n" ::);
        }

        const int s = kt & 1;
        const unsigned KHb = ATT_KH + s*32768;
        const unsigned KLb = KHb + ATT_TILE;
        const unsigned VHb = KHb + 2*ATT_TILE;
        const unsigned VLb = KHb + 3*ATT_TILE;
        const float* fm = fmask + s * 64;

        float sacc[8][4];
        #pragma unroll
        for (int nt = 0; nt < 8; nt++)
            #pragma unroll
            for (int r = 0; r < 4; r++) sacc[nt][r] = 0.0f;

        {
            const int krow = ((grp >> 1) << 3) + li;
            const int kccb = grp & 1;
            #pragma unroll
            for (int q = 0; q < 4; q++) {
                unsigned kb2[8][2];
                #pragma unroll
                for (int p = 0; p < 4; p++)
                    ldsm4(kb2[2*p][0], kb2[2*p][1], kb2[2*p+1][0], kb2[2*p+1][1],
                          smb + swz(KHb, 16*p + krow, 2*q + kccb));
                #pragma unroll
                for (int nt = 0; nt < 8; nt++) mma_bf16(sacc[nt], qfh[q], kb2[nt]);
                #pragma unroll
                for (int nt = 0; nt < 8; nt++) mma_bf16(sacc[nt], qfl[q], kb2[nt]);
                #pragma unroll
                for (int p = 0; p < 4; p++)
                    ldsm4(kb2[2*p][0], kb2[2*p][1], kb2[2*p+1][0], kb2[2*p+1][1],
                          smb + swz(KLb, 16*p + krow, 2*q + kccb));
                #pragma unroll
                for (int nt = 0; nt < 8; nt++) mma_bf16(sacc[nt], qfh[q], kb2[nt]);
            }
        }

        float mx0 = -1e30f, mx1 = -1e30f;
        #pragma unroll
        for (int nt = 0; nt < 8; nt++) {
            float f0 = fm[nt*8 + 2*c];
            float f1 = fm[nt*8 + 2*c + 1];
            sacc[nt][0] = fmaf(sacc[nt][0], 0.125f, f0);
            sacc[nt][1] = fmaf(sacc[nt][1], 0.125f, f1);
            sacc[nt][2] = fmaf(sacc[nt][2], 0.125f, f0);
            sacc[nt][3] = fmaf(sacc[nt][3], 0.125f, f1);
            mx0 = fmaxf(mx0, fmaxf(sacc[nt][0], sacc[nt][1]));
            mx1 = fmaxf(mx1, fmaxf(sacc[nt][2], sacc[nt][3]));
        }
        mx0 = fmaxf(mx0, __shfl_xor_sync(0xffffffff, mx0, 1));
        mx0 = fmaxf(mx0, __shfl_xor_sync(0xffffffff, mx0, 2));
        mx1 = fmaxf(mx1, __shfl_xor_sync(0xffffffff, mx1, 1));
        mx1 = fmaxf(mx1, __shfl_xor_sync(0xffffffff, mx1, 2));

        float nm0 = fmaxf(m0, mx0), nm1 = fmaxf(m1, mx1);
        float sc0 = fexp(m0 - nm0), sc1 = fexp(m1 - nm1);
        m0 = nm0; m1 = nm1;
        l0 *= sc0; l1 *= sc1;
        #pragma unroll
        for (int nt = 0; nt < 8; nt++) {
            oacc[nt][0] *= sc0; oacc[nt][1] *= sc0;
            oacc[nt][2] *= sc1; oacc[nt][3] *= sc1;
        }

        float ls0 = 0.0f, ls1 = 0.0f;
        #pragma unroll
        for (int nt = 0; nt < 8; nt++) {
            float p0 = fexp(sacc[nt][0] - nm0);
            float p1 = fexp(sacc[nt][1] - nm0);
            float p2 = fexp(sacc[nt][2] - nm1);
            float p3 = fexp(sacc[nt][3] - nm1);
            sacc[nt][0] = p0; sacc[nt][1] = p1; sacc[nt][2] = p2; sacc[nt][3] = p3;
            ls0 += p0 + p1; ls1 += p2 + p3;
        }
        ls0 += __shfl_xor_sync(0xffffffff, ls0, 1);
        ls0 += __shfl_xor_sync(0xffffffff, ls0, 2);
        ls1 += __shfl_xor_sync(0xffffffff, ls1, 1);
        ls1 += __shfl_xor_sync(0xffffffff, ls1, 2);
        l0 += ls0; l1 += ls1;

        unsigned pfh[4][4], pfl[4][4];
        #pragma unroll
        for (int j = 0; j < 4; j++) {
            pack_hilo(sacc[2*j][0],   sacc[2*j][1],   pfh[j][0], pfl[j][0]);
            pack_hilo(sacc[2*j][2],   sacc[2*j][3],   pfh[j][1], pfl[j][1]);
            pack_hilo(sacc[2*j+1][0], sacc[2*j+1][1], pfh[j][2], pfl[j][2]);
            pack_hilo(sacc[2*j+1][2], sacc[2*j+1][3], pfh[j][3], pfl[j][3]);
        }

        {
            const int vrow = ((grp & 1) << 3) + li;
            const int vccb = grp >> 1;
            #pragma unroll
            for (int j = 0; j < 4; j++) {
                unsigned vb2[8][2];
                #pragma unroll
                for (int d = 0; d < 8; d += 2)
                    ldsm4t(vb2[d][0], vb2[d][1], vb2[d+1][0], vb2[d+1][1],
                           smb + swz(VHb, 16*j + vrow, d + vccb));
                #pragma unroll
                for (int nt = 0; nt < 8; nt++) mma_bf16(oacc[nt], pfh[j], vb2[nt]);
                #pragma unroll
                for (int nt = 0; nt < 8; nt++) mma_bf16(oacc[nt], pfl[j], vb2[nt]);
                #pragma unroll
                for (int d = 0; d < 8; d += 2)
                    ldsm4t(vb2[d][0], vb2[d][1], vb2[d+1][0], vb2[d+1][1],
                           smb + swz(VLb, 16*j + vrow, d + vccb));
                #pragma unroll
                for (int nt = 0; nt < 8; nt++) mma_bf16(oacc[nt], pfh[j], vb2[nt]);
            }
        }
    }

    float inv0 = 1.0f / l0, inv1 = 1.0f / l1;
    int r0 = qrow0 + warp * 16 + g;
    int r1 = r0 + 8;
    size_t base0 = (size_t)(b * SEQ + r0) * DMODEL + h * DK;
    size_t base1 = (size_t)(b * SEQ + r1) * DMODEL + h * DK;
    #pragma unroll
    for (int nt = 0; nt < 8; nt++) {
        int col = nt * 8 + 2 * c;
        unsigned hi0, lo0, hi1, lo1;
        pack_hilo(oacc[nt][0] * inv0, oacc[nt][1] * inv0, hi0, lo0);
        pack_hilo(oacc[nt][2] * inv1, oacc[nt][3] * inv1, hi1, lo1);
        *(unsigned*)&Ohi[base0 + col] = hi0;
        *(unsigned*)&Olo[base0 + col] = lo0;
        *(unsigned*)&Ohi[base1 + col] = hi1;
        *(unsigned*)&Olo[base1 + col] = lo1;
    }
}

// ---------------------------------------------------------------------------
// Host launch
// ---------------------------------------------------------------------------
extern "C" void kernel_launch(void* const* d_in, const int* in_sizes, int n_in,
                              void* d_out, int out_size)
{
    const float* x     = (const float*)d_in[0];
    const int*   mask  = (const int*)  d_in[1];
    const float* Wq    = (const float*)d_in[2];
    const float* bq    = (const float*)d_in[3];
    const float* Wk    = (const float*)d_in[4];
    const float* bk    = (const float*)d_in[5];
    const float* Wv    = (const float*)d_in[6];
    const float* bv    = (const float*)d_in[7];
    const float* Wo    = (const float*)d_in[8];
    const float* bo    = (const float*)d_in[9];
    const float* W1    = (const float*)d_in[10];
    const float* b1    = (const float*)d_in[11];
    const float* W2    = (const float*)d_in[12];
    const float* b2    = (const float*)d_in[13];
    const float* ln1_g = (const float*)d_in[14];
    const float* ln1_b = (const float*)d_in[15];
    const float* ln2_g = (const float*)d_in[16];
    const float* ln2_b = (const float*)d_in[17];
    float* out = (float*)d_out;

    float* x1;
    __nv_bfloat16 *hh, *hl, *qh, *ql, *kh, *kl, *vh, *vl, *ctxh, *ctxl, *h2h, *h2l, *ffnh, *ffnl;
    __nv_bfloat16 *wqh,*wql,*wkh,*wkl,*wvh,*wvl,*woh,*wol,*w1h,*w1l,*w2h,*w2l;
    cudaGetSymbolAddress((void**)&x1,  g_x1);
    cudaGetSymbolAddress((void**)&hh,  g_hh);
    cudaGetSymbolAddress((void**)&hl,  g_hl);
    cudaGetSymbolAddress((void**)&qh,  g_qh);  cudaGetSymbolAddress((void**)&ql, g_ql);
    cudaGetSymbolAddress((void**)&kh,  g_kh);  cudaGetSymbolAddress((void**)&kl, g_kl);
    cudaGetSymbolAddress((void**)&vh,  g_vh);  cudaGetSymbolAddress((void**)&vl, g_vl);
    cudaGetSymbolAddress((void**)&ctxh, g_ctxh);
    cudaGetSymbolAddress((void**)&ctxl, g_ctxl);
    cudaGetSymbolAddress((void**)&h2h, g_h2h);
    cudaGetSymbolAddress((void**)&h2l, g_h2l);
    cudaGetSymbolAddress((void**)&ffnh, g_ffnh);
    cudaGetSymbolAddress((void**)&ffnl, g_ffnl);
    cudaGetSymbolAddress((void**)&wqh, g_wqh); cudaGetSymbolAddress((void**)&wql, g_wql);
    cudaGetSymbolAddress((void**)&wkh, g_wkh); cudaGetSymbolAddress((void**)&wkl, g_wkl);
    cudaGetSymbolAddress((void**)&wvh, g_wvh); cudaGetSymbolAddress((void**)&wvl, g_wvl);
    cudaGetSymbolAddress((void**)&woh, g_woh); cudaGetSymbolAddress((void**)&wol, g_wol);
    cudaGetSymbolAddress((void**)&w1h, g_w1h); cudaGetSymbolAddress((void**)&w1l, g_w1l);
    cudaGetSymbolAddress((void**)&w2h, g_w2h); cudaGetSymbolAddress((void**)&w2l, g_w2l);

    cudaFuncSetAttribute(attn_mma,      cudaFuncAttributeMaxDynamicSharedMemorySize, ATT_SMEM);
    cudaFuncSetAttribute(mma_gemm2<1>,  cudaFuncAttributeMaxDynamicSharedMemorySize, G2_SMEM);
    cudaFuncSetAttribute(mma_gemm2<2>,  cudaFuncAttributeMaxDynamicSharedMemorySize, G2_SMEM);
    cudaFuncSetAttribute(mma_gemm2<3>,  cudaFuncAttributeMaxDynamicSharedMemorySize, G2_SMEM);

    // 0) weight split+transpose
    dim3 gW(DMODEL/32, DMODEL/32);
    wsplit_kernel<<<gW, 256>>>(Wq, wqh, wql, DMODEL, DMODEL);
    wsplit_kernel<<<gW, 256>>>(Wk, wkh, wkl, DMODEL, DMODEL);
    wsplit_kernel<<<gW, 256>>>(Wv, wvh, wvl, DMODEL, DMODEL);
    wsplit_kernel<<<gW, 256>>>(Wo, woh, wol, DMODEL, DMODEL);
    dim3 gW1(DFF/32, DMODEL/32);
    wsplit_kernel<<<gW1, 256>>>(W1, w1h, w1l, DMODEL, DFF);
    dim3 gW2(DMODEL/32, DFF/32);
    wsplit_kernel<<<gW2, 256>>>(W2, w2h, w2l, DFF, DMODEL);

    // 1) LN1 -> bf16 split
    ln_kernel<<<MROWS, 256>>>(x, ln1_g, ln1_b, hh, hl);

    // 2) QKV projections -> bf16 hi/lo
    dim3 gP(DMODEL/256, MROWS/128);   // (4, 64)
    mma_gemm2<3><<<gP, 256, G2_SMEM>>>(hh, hl, wqh, wql, bq, nullptr, nullptr, qh, ql, MROWS, DMODEL, DMODEL);
    mma_gemm2<3><<<gP, 256, G2_SMEM>>>(hh, hl, wkh, wkl, bk, nullptr, nullptr, kh, kl, MROWS, DMODEL, DMODEL);
    mma_gemm2<3><<<gP, 256, G2_SMEM>>>(hh, hl, wvh, wvl, bv, nullptr, nullptr, vh, vl, MROWS, DMODEL, DMODEL);

    // 3) tensor-core attention -> ctx bf16 hi/lo
    dim3 gA(SEQ/64, NHEADS, BATCH);
    attn_mma<<<gA, 128, ATT_SMEM>>>(qh, ql, kh, kl, vh, vl, mask, ctxh, ctxl);

    // 4) output projection + residual -> x1 (fp32)
    mma_gemm2<1><<<gP, 256, G2_SMEM>>>(ctxh, ctxl, woh, wol, bo, x, x1, nullptr, nullptr, MROWS, DMODEL, DMODEL);

    // 5) LN2 -> bf16 split
    ln_kernel<<<MROWS, 256>>>(x1, ln2_g, ln2_b, h2h, h2l);

    // 6) FFN up + GELU -> ffn bf16 hi/lo
    dim3 gF1(DFF/256, MROWS/128);     // (16, 64)
    mma_gemm2<2><<<gF1, 256, G2_SMEM>>>(h2h, h2l, w1h, w1l, b1, nullptr, nullptr, ffnh, ffnl, MROWS, DFF, DMODEL);

    // 7) FFN down + residual -> out (fp32)
    dim3 gF2(DMODEL/256, MROWS/128);  // (4, 64)
    mma_gemm2<1><<<gF2, 256, G2_SMEM>>>(ffnh, ffnl, w2h, w2l, b2, x1, out, nullptr, nullptr, MROWS, DMODEL, DFF);
}